// round 7
// baseline (speedup 1.0000x reference)
#include <cuda_runtime.h>
#include <cuda_bf16.h>
#include <math.h>
#include <stdint.h>

// ---------------------------------------------------------------------------
// Problem constants
// ---------------------------------------------------------------------------
#define B_SZ   8
#define L_SEQ  2048
#define H_DIM  1024
#define N_DIM  512
#define M_ROWS 16384            // B*L
#define K_TOT  3072             // 3x1024 (split-bf16 folded K)
#define N_OUT  1024

// GEMM config: 128x128 CTA tile, 4 warps (2x2) of 64x64, BK=64, 3-stage cp.async
#define BM 128
#define BN 128
#define BK 64                   // bf16 elems per stage row (128 B data)
#define NSTAGES 3
#define KITERS (K_TOT / BK)     // 48
#define GEMM_THREADS 128

// Padded rows: 64 bf16 = 128B data + 16B pad = 144B. 8 consecutive rows hit
// the 8 distinct 16B chunks mod 128 -> conflict-free ldmatrix.
#define ROWB 144
#define TILEB (128 * ROWB)      // 18432 B per operand tile
#define STAGEB (2 * TILEB)      // 36864 B per stage
#define SMEM_DYN (NSTAGES * STAGEB)   // 110592 B -> 2 CTAs/SM

// ---------------------------------------------------------------------------
// Static device buffers (allocation-free scratch)
// ---------------------------------------------------------------------------
__device__ __nv_bfloat16 g_A[(size_t)M_ROWS * K_TOT];       // 96 MB
__device__ __nv_bfloat16 g_B1[(size_t)N_OUT * K_TOT];       // 6 MB
__device__ __nv_bfloat16 g_B2[(size_t)N_OUT * K_TOT];       // 6 MB
__device__ float         g_scratch[(size_t)M_ROWS * N_OUT]; // 64 MB (Bu f32)

// ---------------------------------------------------------------------------
// PTX helpers (sm_80-class only — legal on base compute_103 target)
// ---------------------------------------------------------------------------
__device__ __forceinline__ uint32_t smem_u32(const void* p) {
    uint32_t a;
    asm("{ .reg .u64 t; cvta.to.shared.u64 t, %1; cvt.u32.u64 %0, t; }" : "=r"(a) : "l"(p));
    return a;
}
__device__ __forceinline__ void cp_async16(uint32_t saddr, const void* g) {
    asm volatile("cp.async.cg.shared.global [%0], [%1], 16;" :: "r"(saddr), "l"(g) : "memory");
}
#define CP_COMMIT() asm volatile("cp.async.commit_group;" ::: "memory")
template <int N> __device__ __forceinline__ void cp_wait_group() {
    asm volatile("cp.async.wait_group %0;" :: "n"(N) : "memory");
}
__device__ __forceinline__ void ldmx4(uint32_t* r, uint32_t addr) {
    asm volatile("ldmatrix.sync.aligned.m8n8.x4.shared.b16 {%0,%1,%2,%3}, [%4];"
                 : "=r"(r[0]), "=r"(r[1]), "=r"(r[2]), "=r"(r[3]) : "r"(addr));
}
__device__ __forceinline__ void mma16816(float* d, const uint32_t* a,
                                         uint32_t b0, uint32_t b1) {
    asm volatile("mma.sync.aligned.m16n8k16.row.col.f32.bf16.bf16.f32 "
                 "{%0,%1,%2,%3}, {%4,%5,%6,%7}, {%8,%9}, {%0,%1,%2,%3};"
                 : "+f"(d[0]), "+f"(d[1]), "+f"(d[2]), "+f"(d[3])
                 : "r"(a[0]), "r"(a[1]), "r"(a[2]), "r"(a[3]), "r"(b0), "r"(b1));
}

// ---------------------------------------------------------------------------
// GEMM: C(f32, 16384x1024) = g_A (bf16, MxK K-major) @ Bmat(bf16, NxK K-major)^T
// ---------------------------------------------------------------------------
__global__ __launch_bounds__(GEMM_THREADS)
void gemm_mma_kernel(const __nv_bfloat16* __restrict__ Bmat,
                     float* __restrict__ C)
{
    extern __shared__ char smem_raw[];
    const uint32_t sbase = smem_u32(smem_raw);

    const int tid  = threadIdx.x;
    const int wid  = tid >> 5;
    const int lane = tid & 31;
    const int wm   = wid >> 1;          // 0..1 (m)
    const int wn   = wid & 1;           // 0..1 (n)
    const int bn0  = blockIdx.x * BN;
    const int bm0  = blockIdx.y * BM;

    const char* gA = (const char*)g_A  + (size_t)bm0 * (K_TOT * 2);
    const char* gB = (const char*)Bmat + (size_t)bn0 * (K_TOT * 2);

    // cp.async mapping: 8 threads per 128B row, 16 rows per pass, 8 passes.
    const int lrow = tid >> 3;           // 0..15
    const int lcol = (tid & 7) * 16;     // 0..112

    auto load_stage = [&](int s, int kiter) {
        const uint32_t sa = sbase + s * STAGEB;
        const uint32_t sb = sa + TILEB;
        const size_t kb = (size_t)kiter * (BK * 2);
#pragma unroll
        for (int p = 0; p < 8; p++) {
            const int r = lrow + p * 16;
            const size_t gofs = (size_t)r * (K_TOT * 2) + kb + lcol;
            const uint32_t sofs = r * ROWB + lcol;
            cp_async16(sa + sofs, gA + gofs);
            cp_async16(sb + sofs, gB + gofs);
        }
    };

    // ldmatrix per-thread base offsets
    const int l16 = lane & 15;
    const int lh  = lane >> 4;
    const uint32_t a_off = (uint32_t)((wm * 64 + l16) * ROWB + lh * 16);
    const uint32_t b_off = (uint32_t)((wn * 64 + l16) * ROWB + lh * 16);

    float acc[4][8][4];
#pragma unroll
    for (int mi = 0; mi < 4; mi++)
#pragma unroll
        for (int ni = 0; ni < 8; ni++)
#pragma unroll
            for (int q = 0; q < 4; q++) acc[mi][ni][q] = 0.f;

    // Prologue: fill NSTAGES-1 stages
#pragma unroll
    for (int s = 0; s < NSTAGES - 1; s++) { load_stage(s, s); CP_COMMIT(); }

    for (int j = 0; j < KITERS; j++) {
        cp_wait_group<NSTAGES - 2>();
        __syncthreads();

        const int s = j - (j / NSTAGES) * NSTAGES;      // j % 3
        const int jn = j + NSTAGES - 1;
        if (jn < KITERS) {
            load_stage(jn - (jn / NSTAGES) * NSTAGES, jn);
        }
        CP_COMMIT();

        const uint32_t sa = sbase + s * STAGEB;
        const uint32_t sb = sa + TILEB;
#pragma unroll
        for (int ks = 0; ks < 4; ks++) {                 // 4 x k16 per stage
            const uint32_t kb = ks * 32;                  // byte offset
            uint32_t ar[4][4];
#pragma unroll
            for (int mi = 0; mi < 4; mi++)
                ldmx4(ar[mi], sa + a_off + mi * 16 * ROWB + kb);
            uint32_t br[4][4];
#pragma unroll
            for (int ni = 0; ni < 4; ni++)
                ldmx4(br[ni], sb + b_off + ni * 16 * ROWB + kb);
#pragma unroll
            for (int mi = 0; mi < 4; mi++) {
#pragma unroll
                for (int ni = 0; ni < 4; ni++) {
                    mma16816(acc[mi][2 * ni],     ar[mi], br[ni][0], br[ni][2]);
                    mma16816(acc[mi][2 * ni + 1], ar[mi], br[ni][1], br[ni][3]);
                }
            }
        }
    }

    // Epilogue: m16n8 d-frag: d0,d1 -> (lane/4, 2*(lane%4)); d2,d3 -> row+8
    const int r0 = lane >> 2;
    const int c0 = (lane & 3) * 2;
    const int mbase = bm0 + wm * 64;
    const int nbase = bn0 + wn * 64;
#pragma unroll
    for (int mi = 0; mi < 4; mi++) {
#pragma unroll
        for (int ni = 0; ni < 8; ni++) {
            float* p = C + (size_t)(mbase + mi * 16 + r0) * N_OUT + nbase + ni * 8 + c0;
            *(float2*)p = make_float2(acc[mi][ni][0], acc[mi][ni][1]);
            *(float2*)(p + 8 * N_OUT) = make_float2(acc[mi][ni][2], acc[mi][ni][3]);
        }
    }
}

// ---------------------------------------------------------------------------
// pack_A1: u (f32, 16384x1024) -> g_A = [hi | hi | lo] (bf16, 16384x3072)
// ---------------------------------------------------------------------------
__global__ __launch_bounds__(256)
void pack_A1_kernel(const float* __restrict__ u)
{
    const int idx = blockIdx.x * blockDim.x + threadIdx.x;   // over M_ROWS*512 pairs
    if (idx >= M_ROWS * 512) return;
    const int r  = idx >> 9;
    const int np = idx & 511;
    const float2 v = *(const float2*)(u + (size_t)r * 1024 + 2 * np);
    __nv_bfloat16 h0 = __float2bfloat16_rn(v.x);
    __nv_bfloat16 h1 = __float2bfloat16_rn(v.y);
    __nv_bfloat162 hi; hi.x = h0; hi.y = h1;
    __nv_bfloat162 lo;
    lo.x = __float2bfloat16_rn(v.x - __bfloat162float(h0));
    lo.y = __float2bfloat16_rn(v.y - __bfloat162float(h1));
    __nv_bfloat162* row = (__nv_bfloat162*)(g_A + (size_t)r * K_TOT);
    row[np]        = hi;      // k = 2np
    row[512 + np]  = hi;      // k = 1024 + 2np
    row[1024 + np] = lo;      // k = 2048 + 2np
}

// ---------------------------------------------------------------------------
// pack_B: weights -> B'[n][k] = [hi(k) | lo(k-1024) | hi(k-2048)] (K-major)
// ---------------------------------------------------------------------------
__global__ __launch_bounds__(256)
void pack_B1_kernel(const float* __restrict__ Br, const float* __restrict__ Bi)
{
    __shared__ float tile[32][33];
    const int k0 = blockIdx.y * 32, n0 = blockIdx.x * 32;
    const int tx = threadIdx.x, ty = threadIdx.y;       // (32, 8)
#pragma unroll
    for (int j = 0; j < 32; j += 8) {
        const int k = k0 + ty + j, n = n0 + tx;
        tile[ty + j][tx] = (n < N_DIM) ? Br[(size_t)k * N_DIM + n]
                                       : Bi[(size_t)k * N_DIM + (n - N_DIM)];
    }
    __syncthreads();
#pragma unroll
    for (int j = 0; j < 32; j += 8) {
        const int n = n0 + ty + j, k = k0 + tx;
        const float w = tile[tx][ty + j];
        __nv_bfloat16 h = __float2bfloat16_rn(w);
        __nv_bfloat16 l = __float2bfloat16_rn(w - __bfloat162float(h));
        __nv_bfloat16* row = g_B1 + (size_t)n * K_TOT;
        row[k]        = h;
        row[1024 + k] = l;
        row[2048 + k] = h;
    }
}

__global__ __launch_bounds__(256)
void pack_B2_kernel(const float* __restrict__ Cr, const float* __restrict__ Ci)
{
    __shared__ float tile[32][33];
    const int k0 = blockIdx.y * 32, n0 = blockIdx.x * 32;
    const int tx = threadIdx.x, ty = threadIdx.y;
#pragma unroll
    for (int j = 0; j < 32; j += 8) {
        const int k = k0 + ty + j, n = n0 + tx;
        tile[ty + j][tx] = (k < N_DIM) ? Cr[(size_t)k * N_OUT + n]
                                       : -Ci[(size_t)(k - N_DIM) * N_OUT + n];
    }
    __syncthreads();
#pragma unroll
    for (int j = 0; j < 32; j += 8) {
        const int n = n0 + ty + j, k = k0 + tx;
        const float w = tile[tx][ty + j];
        __nv_bfloat16 h = __float2bfloat16_rn(w);
        __nv_bfloat16 l = __float2bfloat16_rn(w - __bfloat162float(h));
        __nv_bfloat16* row = g_B2 + (size_t)n * K_TOT;
        row[k]        = h;
        row[1024 + k] = l;
        row[2048 + k] = h;
    }
}

// ---------------------------------------------------------------------------
// Elementwise + batch cumsum, fused with split-bf16 pack of x into g_A.
// g_scratch row r=b*L+l: cols [0,512)=Bu_r, [512,1024)=Bu_i.
// ---------------------------------------------------------------------------
__global__ __launch_bounds__(256)
void lru_elem_pack_kernel(const int* __restrict__ lengths,
                          const float* __restrict__ nu_log,
                          const float* __restrict__ theta_log)
{
    const int idx = blockIdx.x * blockDim.x + threadIdx.x;   // L_SEQ * 256 pairs
    if (idx >= L_SEQ * 256) return;
    const int l  = idx >> 8;
    const int np = idx & 255;
    const int n  = 2 * np;

    float lamlog[2], argv[2];
#pragma unroll
    for (int c = 0; c < 2; c++) {
        const float lam_mod = expf(-expf(__ldg(&nu_log[n + c])));
        lamlog[c] = logf(lam_mod);
        argv[c]   = expf(__ldg(&theta_log[n + c]));
    }

    float2 vr[B_SZ], vi[B_SZ];
#pragma unroll
    for (int b = 0; b < B_SZ; b++) {
        const float* sr = g_scratch + ((size_t)(b * L_SEQ + l)) * N_OUT;
        vr[b] = *(const float2*)(sr + n);
        vi[b] = *(const float2*)(sr + N_DIM + n);
    }

    float xr0 = 0.f, xr1 = 0.f, xi0 = 0.f, xi1 = 0.f;
#pragma unroll
    for (int b = 0; b < B_SZ; b++) {
        const float e = fmaxf((float)__ldg(&lengths[b]) - (float)(l + 1), 0.f);
        float mag, s, c_;
        mag = expf(e * lamlog[0]); sincosf(e * argv[0], &s, &c_);
        float Lr = mag * c_, Li = mag * s;
        xr0 += Lr * vr[b].x - Li * vi[b].x;
        xi0 += Lr * vi[b].x + Li * vr[b].x;
        mag = expf(e * lamlog[1]); sincosf(e * argv[1], &s, &c_);
        Lr = mag * c_; Li = mag * s;
        xr1 += Lr * vr[b].y - Li * vi[b].y;
        xi1 += Lr * vi[b].y + Li * vr[b].y;

        __nv_bfloat16 hr0 = __float2bfloat16_rn(xr0), hr1 = __float2bfloat16_rn(xr1);
        __nv_bfloat16 hi0 = __float2bfloat16_rn(xi0), hi1 = __float2bfloat16_rn(xi1);
        __nv_bfloat162 hr2; hr2.x = hr0; hr2.y = hr1;
        __nv_bfloat162 hi2; hi2.x = hi0; hi2.y = hi1;
        __nv_bfloat162 lr2, li2;
        lr2.x = __float2bfloat16_rn(xr0 - __bfloat162float(hr0));
        lr2.y = __float2bfloat16_rn(xr1 - __bfloat162float(hr1));
        li2.x = __float2bfloat16_rn(xi0 - __bfloat162float(hi0));
        li2.y = __float2bfloat16_rn(xi1 - __bfloat162float(hi1));

        __nv_bfloat162* row = (__nv_bfloat162*)(g_A + ((size_t)(b * L_SEQ + l)) * K_TOT);
        row[np]         = hr2;   // k = n          (hi xr)
        row[256 + np]   = hi2;   // k = 512 + n    (hi xi)
        row[512 + np]   = hr2;   // k = 1024 + n
        row[768 + np]   = hi2;   // k = 1536 + n
        row[1024 + np]  = lr2;   // k = 2048 + n   (lo xr)
        row[1280 + np]  = li2;   // k = 2560 + n   (lo xi)
    }
}

// ---------------------------------------------------------------------------
// Launch. Inputs: 0:u 1:lenghts 2:nu_log 3:theta_log 4:Br 5:Bi 6:Cr 7:Ci
// Output: y (B,L,H) f32
// ---------------------------------------------------------------------------
extern "C" void kernel_launch(void* const* d_in, const int* in_sizes, int n_in,
                              void* d_out, int out_size)
{
    const float* u         = (const float*)d_in[0];
    const int*   lengths   = (const int*)d_in[1];
    const float* nu_log    = (const float*)d_in[2];
    const float* theta_log = (const float*)d_in[3];
    const float* Br        = (const float*)d_in[4];
    const float* Bi        = (const float*)d_in[5];
    const float* Cr        = (const float*)d_in[6];
    const float* Ci        = (const float*)d_in[7];
    float* y = (float*)d_out;

    cudaFuncSetAttribute(gemm_mma_kernel,
                         cudaFuncAttributeMaxDynamicSharedMemorySize, SMEM_DYN);

    void *pB1 = nullptr, *pB2 = nullptr, *pS = nullptr;
    cudaGetSymbolAddress(&pB1, g_B1);
    cudaGetSymbolAddress(&pB2, g_B2);
    cudaGetSymbolAddress(&pS,  g_scratch);

    // 1. Pack A' and both weight matrices
    pack_A1_kernel<<<(M_ROWS * 512) / 256, 256>>>(u);
    dim3 pb(32, 8), pg(32, 32);
    pack_B1_kernel<<<pg, pb>>>(Br, Bi);
    pack_B2_kernel<<<pg, pb>>>(Cr, Ci);

    // 2. GEMM1: Bu = A' @ B1'^T  -> g_scratch (f32)
    dim3 gg(N_OUT / BN, M_ROWS / BM);   // (8, 128)
    gemm_mma_kernel<<<gg, GEMM_THREADS, SMEM_DYN>>>(
        (const __nv_bfloat16*)pB1, (float*)pS);

    // 3. Elementwise Lambda^e * Bu + batch cumsum, packed back into g_A
    lru_elem_pack_kernel<<<(L_SEQ * 256) / 256, 256>>>(lengths, nu_log, theta_log);

    // 4. GEMM2: y = A' @ B2'^T
    gemm_mma_kernel<<<gg, GEMM_THREADS, SMEM_DYN>>>(
        (const __nv_bfloat16*)pB2, y);
}

// round 8
// speedup vs baseline: 1.5705x; 1.5705x over previous
#include <cuda_runtime.h>
#include <cuda_bf16.h>
#include <math.h>
#include <stdint.h>

// ---------------------------------------------------------------------------
// Problem constants
// ---------------------------------------------------------------------------
#define B_SZ   8
#define L_SEQ  2048
#define H_DIM  1024
#define N_DIM  512
#define M_ROWS 16384            // B*L
#define K_A    2048             // A stored as [hi | lo] (dedup'd)
#define K_B    3072             // B stored as [hi ; lo ; hi]
#define N_OUT  1024

// GEMM config: 128x128 CTA tile, 8 warps (2m x 4n) of 64x32, BK=64, 3 stages
#define BM 128
#define BN 128
#define BK 64                   // bf16 elems per stage row (128 B data)
#define NSTAGES 3
#define KITERS (K_B / BK)       // 48 MMA k-iterations (A offsets remapped)
#define GEMM_THREADS 256

// Padded rows: 64 bf16 = 128B data + 16B pad = 144B. 8 consecutive rows hit
// the 8 distinct 16B chunks mod 128 -> conflict-free ldmatrix.
#define ROWB 144
#define TILEB (128 * ROWB)      // 18432 B per operand tile
#define STAGEB (2 * TILEB)      // 36864 B per stage
#define SMEM_DYN (NSTAGES * STAGEB)   // 110592 B -> 2 CTAs/SM, 16 warps/SM

// ---------------------------------------------------------------------------
// Static device buffers (allocation-free scratch)
// ---------------------------------------------------------------------------
__device__ __nv_bfloat16 g_A[(size_t)M_ROWS * K_A];         // 64 MB
__device__ __nv_bfloat16 g_B1[(size_t)N_OUT * K_B];         // 6 MB
__device__ __nv_bfloat16 g_B2[(size_t)N_OUT * K_B];         // 6 MB
__device__ float         g_scratch[(size_t)M_ROWS * N_OUT]; // 64 MB (Bu f32)

// ---------------------------------------------------------------------------
// PTX helpers (sm_80-class only — legal on base compute_103 target)
// ---------------------------------------------------------------------------
__device__ __forceinline__ uint32_t smem_u32(const void* p) {
    uint32_t a;
    asm("{ .reg .u64 t; cvta.to.shared.u64 t, %1; cvt.u32.u64 %0, t; }" : "=r"(a) : "l"(p));
    return a;
}
__device__ __forceinline__ void cp_async16(uint32_t saddr, const void* g) {
    asm volatile("cp.async.cg.shared.global [%0], [%1], 16;" :: "r"(saddr), "l"(g) : "memory");
}
#define CP_COMMIT() asm volatile("cp.async.commit_group;" ::: "memory")
template <int N> __device__ __forceinline__ void cp_wait_group() {
    asm volatile("cp.async.wait_group %0;" :: "n"(N) : "memory");
}
__device__ __forceinline__ void ldmx4(uint32_t* r, uint32_t addr) {
    asm volatile("ldmatrix.sync.aligned.m8n8.x4.shared.b16 {%0,%1,%2,%3}, [%4];"
                 : "=r"(r[0]), "=r"(r[1]), "=r"(r[2]), "=r"(r[3]) : "r"(addr));
}
__device__ __forceinline__ void mma16816(float* d, const uint32_t* a,
                                         uint32_t b0, uint32_t b1) {
    asm volatile("mma.sync.aligned.m16n8k16.row.col.f32.bf16.bf16.f32 "
                 "{%0,%1,%2,%3}, {%4,%5,%6,%7}, {%8,%9}, {%0,%1,%2,%3};"
                 : "+f"(d[0]), "+f"(d[1]), "+f"(d[2]), "+f"(d[3])
                 : "r"(a[0]), "r"(a[1]), "r"(a[2]), "r"(a[3]), "r"(b0), "r"(b1));
}

// ---------------------------------------------------------------------------
// GEMM: C(f32, 16384x1024) = g_A (bf16 [hi|lo], K remapped) @ Bmat^T
// MMA k-iter kiter in [0,48): A uses columns (kiter<16 ? kiter : kiter-16)*64,
// so kiter 0-15 -> A-hi vs B-hi, 16-31 -> A-hi vs B-lo, 32-47 -> A-lo vs B-hi.
// ---------------------------------------------------------------------------
__global__ __launch_bounds__(GEMM_THREADS, 2)
void gemm_mma_kernel(const __nv_bfloat16* __restrict__ Bmat,
                     float* __restrict__ C)
{
    extern __shared__ char smem_raw[];
    const uint32_t sbase = smem_u32(smem_raw);

    const int tid  = threadIdx.x;
    const int wid  = tid >> 5;
    const int lane = tid & 31;
    const int wm   = wid >> 2;          // 0..1 (m)
    const int wn   = wid & 3;           // 0..3 (n)
    const int bn0  = blockIdx.x * BN;
    const int bm0  = blockIdx.y * BM;

    const char* gA = (const char*)g_A  + (size_t)bm0 * (K_A * 2);
    const char* gB = (const char*)Bmat + (size_t)bn0 * (K_B * 2);

    // cp.async mapping: 8 threads per 128B row, 32 rows per pass, 4 passes.
    const int lrow = tid >> 3;           // 0..31
    const int lcol = (tid & 7) * 16;     // 0..112

    auto load_stage = [&](int s, int kiter) {
        const uint32_t sa = sbase + s * STAGEB;
        const uint32_t sb = sa + TILEB;
        const int ka = (kiter < 16) ? kiter : (kiter - 16);  // A hi-block dedup
        const size_t kab = (size_t)ka * (BK * 2);
        const size_t kbb = (size_t)kiter * (BK * 2);
#pragma unroll
        for (int p = 0; p < 4; p++) {
            const int r = lrow + p * 32;
            const uint32_t sofs = r * ROWB + lcol;
            cp_async16(sa + sofs, gA + (size_t)r * (K_A * 2) + kab + lcol);
            cp_async16(sb + sofs, gB + (size_t)r * (K_B * 2) + kbb + lcol);
        }
    };

    // ldmatrix per-thread base offsets
    const int l16 = lane & 15;
    const int lh  = lane >> 4;
    const uint32_t a_off = (uint32_t)((wm * 64 + l16) * ROWB + lh * 16);
    const uint32_t b_off = (uint32_t)((wn * 32 + l16) * ROWB + lh * 16);

    float acc[4][4][4];
#pragma unroll
    for (int mi = 0; mi < 4; mi++)
#pragma unroll
        for (int ni = 0; ni < 4; ni++)
#pragma unroll
            for (int q = 0; q < 4; q++) acc[mi][ni][q] = 0.f;

    // Prologue: fill NSTAGES-1 stages
#pragma unroll
    for (int s = 0; s < NSTAGES - 1; s++) { load_stage(s, s); CP_COMMIT(); }

    for (int j = 0; j < KITERS; j++) {
        cp_wait_group<NSTAGES - 2>();
        __syncthreads();

        const int s = j - (j / NSTAGES) * NSTAGES;      // j % 3
        const int jn = j + NSTAGES - 1;
        if (jn < KITERS) {
            load_stage(jn - (jn / NSTAGES) * NSTAGES, jn);
        }
        CP_COMMIT();

        const uint32_t sa = sbase + s * STAGEB;
        const uint32_t sb = sa + TILEB;
#pragma unroll
        for (int ks = 0; ks < 4; ks++) {                 // 4 x k16 per stage
            const uint32_t kb = ks * 32;                  // byte offset
            uint32_t ar[4][4];
#pragma unroll
            for (int mi = 0; mi < 4; mi++)
                ldmx4(ar[mi], sa + a_off + mi * 16 * ROWB + kb);
            uint32_t br0[4], br1[4];
            ldmx4(br0, sb + b_off + kb);
            ldmx4(br1, sb + b_off + 16 * ROWB + kb);
#pragma unroll
            for (int mi = 0; mi < 4; mi++) {
                mma16816(acc[mi][0], ar[mi], br0[0], br0[2]);
                mma16816(acc[mi][1], ar[mi], br0[1], br0[3]);
                mma16816(acc[mi][2], ar[mi], br1[0], br1[2]);
                mma16816(acc[mi][3], ar[mi], br1[1], br1[3]);
            }
        }
    }

    // Epilogue: m16n8 d-frag: d0,d1 -> (lane/4, 2*(lane%4)); d2,d3 -> row+8
    const int r0 = lane >> 2;
    const int c0 = (lane & 3) * 2;
    const int mbase = bm0 + wm * 64;
    const int nbase = bn0 + wn * 32;
#pragma unroll
    for (int mi = 0; mi < 4; mi++) {
#pragma unroll
        for (int ni = 0; ni < 4; ni++) {
            float* p = C + (size_t)(mbase + mi * 16 + r0) * N_OUT + nbase + ni * 8 + c0;
            *(float2*)p = make_float2(acc[mi][ni][0], acc[mi][ni][1]);
            *(float2*)(p + 8 * N_OUT) = make_float2(acc[mi][ni][2], acc[mi][ni][3]);
        }
    }
}

// ---------------------------------------------------------------------------
// pack_A1: u (f32, 16384x1024) -> g_A = [hi | lo] (bf16, 16384x2048)
// ---------------------------------------------------------------------------
__global__ __launch_bounds__(256)
void pack_A1_kernel(const float* __restrict__ u)
{
    const int idx = blockIdx.x * blockDim.x + threadIdx.x;   // over M_ROWS*512 pairs
    if (idx >= M_ROWS * 512) return;
    const int r  = idx >> 9;
    const int np = idx & 511;
    const float2 v = *(const float2*)(u + (size_t)r * 1024 + 2 * np);
    __nv_bfloat16 h0 = __float2bfloat16_rn(v.x);
    __nv_bfloat16 h1 = __float2bfloat16_rn(v.y);
    __nv_bfloat162 hi; hi.x = h0; hi.y = h1;
    __nv_bfloat162 lo;
    lo.x = __float2bfloat16_rn(v.x - __bfloat162float(h0));
    lo.y = __float2bfloat16_rn(v.y - __bfloat162float(h1));
    __nv_bfloat162* row = (__nv_bfloat162*)(g_A + (size_t)r * K_A);
    row[np]       = hi;       // k = 2np
    row[512 + np] = lo;       // k = 1024 + 2np
}

// ---------------------------------------------------------------------------
// pack_B: weights -> B'[n][k] = [hi(k) | lo(k-1024) | hi(k-2048)] (K-major)
// ---------------------------------------------------------------------------
__global__ __launch_bounds__(256)
void pack_B1_kernel(const float* __restrict__ Br, const float* __restrict__ Bi)
{
    __shared__ float tile[32][33];
    const int k0 = blockIdx.y * 32, n0 = blockIdx.x * 32;
    const int tx = threadIdx.x, ty = threadIdx.y;       // (32, 8)
#pragma unroll
    for (int j = 0; j < 32; j += 8) {
        const int k = k0 + ty + j, n = n0 + tx;
        tile[ty + j][tx] = (n < N_DIM) ? Br[(size_t)k * N_DIM + n]
                                       : Bi[(size_t)k * N_DIM + (n - N_DIM)];
    }
    __syncthreads();
#pragma unroll
    for (int j = 0; j < 32; j += 8) {
        const int n = n0 + ty + j, k = k0 + tx;
        const float w = tile[tx][ty + j];
        __nv_bfloat16 h = __float2bfloat16_rn(w);
        __nv_bfloat16 l = __float2bfloat16_rn(w - __bfloat162float(h));
        __nv_bfloat16* row = g_B1 + (size_t)n * K_B;
        row[k]        = h;
        row[1024 + k] = l;
        row[2048 + k] = h;
    }
}

__global__ __launch_bounds__(256)
void pack_B2_kernel(const float* __restrict__ Cr, const float* __restrict__ Ci)
{
    __shared__ float tile[32][33];
    const int k0 = blockIdx.y * 32, n0 = blockIdx.x * 32;
    const int tx = threadIdx.x, ty = threadIdx.y;
#pragma unroll
    for (int j = 0; j < 32; j += 8) {
        const int k = k0 + ty + j, n = n0 + tx;
        tile[ty + j][tx] = (k < N_DIM) ? Cr[(size_t)k * N_OUT + n]
                                       : -Ci[(size_t)(k - N_DIM) * N_OUT + n];
    }
    __syncthreads();
#pragma unroll
    for (int j = 0; j < 32; j += 8) {
        const int n = n0 + ty + j, k = k0 + tx;
        const float w = tile[tx][ty + j];
        __nv_bfloat16 h = __float2bfloat16_rn(w);
        __nv_bfloat16 l = __float2bfloat16_rn(w - __bfloat162float(h));
        __nv_bfloat16* row = g_B2 + (size_t)n * K_B;
        row[k]        = h;
        row[1024 + k] = l;
        row[2048 + k] = h;
    }
}

// ---------------------------------------------------------------------------
// Elementwise + batch cumsum, fused with split-bf16 pack of x into g_A [hi|lo].
// g_scratch row r=b*L+l: cols [0,512)=Bu_r, [512,1024)=Bu_i.
// g_A row r: k=[0,512)=hi(xr), [512,1024)=hi(xi), [1024,1536)=lo(xr),
//            [1536,2048)=lo(xi).
// ---------------------------------------------------------------------------
__global__ __launch_bounds__(256)
void lru_elem_pack_kernel(const int* __restrict__ lengths,
                          const float* __restrict__ nu_log,
                          const float* __restrict__ theta_log)
{
    const int idx = blockIdx.x * blockDim.x + threadIdx.x;   // L_SEQ * 256 pairs
    if (idx >= L_SEQ * 256) return;
    const int l  = idx >> 8;
    const int np = idx & 255;
    const int n  = 2 * np;

    float lamlog[2], argv[2];
#pragma unroll
    for (int c = 0; c < 2; c++) {
        const float lam_mod = expf(-expf(__ldg(&nu_log[n + c])));
        lamlog[c] = logf(lam_mod);
        argv[c]   = expf(__ldg(&theta_log[n + c]));
    }

    float2 vr[B_SZ], vi[B_SZ];
#pragma unroll
    for (int b = 0; b < B_SZ; b++) {
        const float* sr = g_scratch + ((size_t)(b * L_SEQ + l)) * N_OUT;
        vr[b] = *(const float2*)(sr + n);
        vi[b] = *(const float2*)(sr + N_DIM + n);
    }

    float xr0 = 0.f, xr1 = 0.f, xi0 = 0.f, xi1 = 0.f;
#pragma unroll
    for (int b = 0; b < B_SZ; b++) {
        const float e = fmaxf((float)__ldg(&lengths[b]) - (float)(l + 1), 0.f);
        float mag, s, c_;
        mag = expf(e * lamlog[0]); sincosf(e * argv[0], &s, &c_);
        float Lr = mag * c_, Li = mag * s;
        xr0 += Lr * vr[b].x - Li * vi[b].x;
        xi0 += Lr * vi[b].x + Li * vr[b].x;
        mag = expf(e * lamlog[1]); sincosf(e * argv[1], &s, &c_);
        Lr = mag * c_; Li = mag * s;
        xr1 += Lr * vr[b].y - Li * vi[b].y;
        xi1 += Lr * vi[b].y + Li * vr[b].y;

        __nv_bfloat16 hr0 = __float2bfloat16_rn(xr0), hr1 = __float2bfloat16_rn(xr1);
        __nv_bfloat16 hi0 = __float2bfloat16_rn(xi0), hi1 = __float2bfloat16_rn(xi1);
        __nv_bfloat162 hr2; hr2.x = hr0; hr2.y = hr1;
        __nv_bfloat162 hi2; hi2.x = hi0; hi2.y = hi1;
        __nv_bfloat162 lr2, li2;
        lr2.x = __float2bfloat16_rn(xr0 - __bfloat162float(hr0));
        lr2.y = __float2bfloat16_rn(xr1 - __bfloat162float(hr1));
        li2.x = __float2bfloat16_rn(xi0 - __bfloat162float(hi0));
        li2.y = __float2bfloat16_rn(xi1 - __bfloat162float(hi1));

        __nv_bfloat162* row = (__nv_bfloat162*)(g_A + ((size_t)(b * L_SEQ + l)) * K_A);
        row[np]        = hr2;   // k = n           (hi xr)
        row[256 + np]  = hi2;   // k = 512 + n     (hi xi)
        row[512 + np]  = lr2;   // k = 1024 + n    (lo xr)
        row[768 + np]  = li2;   // k = 1536 + n    (lo xi)
    }
}

// ---------------------------------------------------------------------------
// Launch. Inputs: 0:u 1:lenghts 2:nu_log 3:theta_log 4:Br 5:Bi 6:Cr 7:Ci
// Output: y (B,L,H) f32
// ---------------------------------------------------------------------------
extern "C" void kernel_launch(void* const* d_in, const int* in_sizes, int n_in,
                              void* d_out, int out_size)
{
    const float* u         = (const float*)d_in[0];
    const int*   lengths   = (const int*)d_in[1];
    const float* nu_log    = (const float*)d_in[2];
    const float* theta_log = (const float*)d_in[3];
    const float* Br        = (const float*)d_in[4];
    const float* Bi        = (const float*)d_in[5];
    const float* Cr        = (const float*)d_in[6];
    const float* Ci        = (const float*)d_in[7];
    float* y = (float*)d_out;

    cudaFuncSetAttribute(gemm_mma_kernel,
                         cudaFuncAttributeMaxDynamicSharedMemorySize, SMEM_DYN);

    void *pB1 = nullptr, *pB2 = nullptr, *pS = nullptr;
    cudaGetSymbolAddress(&pB1, g_B1);
    cudaGetSymbolAddress(&pB2, g_B2);
    cudaGetSymbolAddress(&pS,  g_scratch);

    // 1. Pack A' and both weight matrices
    pack_A1_kernel<<<(M_ROWS * 512) / 256, 256>>>(u);
    dim3 pb(32, 8), pg(32, 32);
    pack_B1_kernel<<<pg, pb>>>(Br, Bi);
    pack_B2_kernel<<<pg, pb>>>(Cr, Ci);

    // 2. GEMM1: Bu = A' @ B1'^T  -> g_scratch (f32)
    dim3 gg(N_OUT / BN, M_ROWS / BM);   // (8, 128)
    gemm_mma_kernel<<<gg, GEMM_THREADS, SMEM_DYN>>>(
        (const __nv_bfloat16*)pB1, (float*)pS);

    // 3. Elementwise Lambda^e * Bu + batch cumsum, packed back into g_A
    lru_elem_pack_kernel<<<(L_SEQ * 256) / 256, 256>>>(lengths, nu_log, theta_log);

    // 4. GEMM2: y = A' @ B2'^T
    gemm_mma_kernel<<<gg, GEMM_THREADS, SMEM_DYN>>>(
        (const __nv_bfloat16*)pB2, y);
}